// round 1
// baseline (speedup 1.0000x reference)
#include <cuda_runtime.h>

#define N_NODES   8192
#define T_TYPES   4
#define E_EDGES   131072        // = 2^17
#define H_HEADS   4
#define D_DIM     32
#define NEG_SLOPE 0.2f

#define HASH_BITS 22
#define HASH_SIZE (1u << HASH_BITS)
#define HASH_MASK (HASH_SIZE - 1u)
#define EMPTY_KEY 0xFFFFFFFFu

// Scratch (static device globals — no allocation in kernel_launch)
__device__ unsigned int g_keys[HASH_SIZE];
__device__ unsigned int g_cnts[HASH_SIZE];
__device__ float g_denom[H_HEADS * N_NODES];   // sum of (exp-1) per (head,row)
__device__ float g_num  [H_HEADS * N_NODES];   // sum of (exp-1)*s_j per (head,row)
__device__ float g_wsrc[H_HEADS];
__device__ float g_wtgt[H_HEADS];
__device__ float g_embterm[H_HEADS * T_TYPES];
__device__ float g_stotal;

// ---------------------------------------------------------------------------
// 1) Clear hash table + accumulators (must run every call: graph-replayable)
// ---------------------------------------------------------------------------
__global__ void k_clear() {
    unsigned int i      = blockIdx.x * blockDim.x + threadIdx.x;
    unsigned int stride = gridDim.x * blockDim.x;
    for (unsigned int s = i; s < HASH_SIZE; s += stride) {
        g_keys[s] = EMPTY_KEY;
        g_cnts[s] = 0u;
    }
    for (unsigned int s = i; s < H_HEADS * N_NODES; s += stride) {
        g_denom[s] = 0.f;
        g_num[s]   = 0.f;
    }
}

// ---------------------------------------------------------------------------
// 2) Tiny per-head parameters + total score sum (single block)
// ---------------------------------------------------------------------------
__global__ void k_params(const float* __restrict__ scores,
                         const float* __restrict__ emb,
                         const float* __restrict__ W) {
    __shared__ float red[256];
    int tid = threadIdx.x;

    float s = 0.f;
    for (int i = tid; i < N_NODES; i += 256) s += scores[i];
    red[tid] = s;
    __syncthreads();
    for (int o = 128; o > 0; o >>= 1) {
        if (tid < o) red[tid] += red[tid + o];
        __syncthreads();
    }
    if (tid == 0) g_stotal = red[0];

    if (tid < H_HEADS * T_TYPES) {
        int h = tid / T_TYPES, t = tid % T_TYPES;
        float acc = 0.f;
        #pragma unroll
        for (int d = 0; d < D_DIM; d++)
            acc += emb[t * D_DIM + d] * W[h * (D_DIM + 2) + 1 + d];
        g_embterm[h * T_TYPES + t] = acc;
    }
    if (tid >= 32 && tid < 32 + H_HEADS) {
        int h = tid - 32;
        g_wsrc[h] = W[h * (D_DIM + 2)];
        g_wtgt[h] = W[h * (D_DIM + 2) + D_DIM + 1];
    }
}

// ---------------------------------------------------------------------------
// 3) Insert all edges into the hash: key=(src<<13)|tgt, packed per-type count
// ---------------------------------------------------------------------------
__global__ void k_insert(const int* __restrict__ ei) {
    int id = blockIdx.x * blockDim.x + threadIdx.x;
    if (id >= T_TYPES * E_EDGES) return;
    int t = id >> 17;             // E_EDGES = 2^17
    int e = id & (E_EDGES - 1);
    // edge_index layout (T, 2, E)
    unsigned int src = (unsigned int)ei[(t * 2    ) * E_EDGES + e];
    unsigned int tgt = (unsigned int)ei[(t * 2 + 1) * E_EDGES + e];

    unsigned int key = (src << 13) | tgt;
    unsigned int h = key * 2654435761u;
    h ^= h >> 15;
    unsigned int slot = h & HASH_MASK;

    while (true) {
        unsigned int old = atomicCAS(&g_keys[slot], EMPTY_KEY, key);
        if (old == EMPTY_KEY || old == key) break;
        slot = (slot + 1) & HASH_MASK;
    }
    atomicAdd(&g_cnts[slot], 1u << (t * 8));
}

// ---------------------------------------------------------------------------
// 4) Scan occupied slots: reconstruct summed a_ij per head, accumulate
//    (exp(leaky(a))-1) and (exp(leaky(a))-1)*s_j per (head, row)
// ---------------------------------------------------------------------------
__global__ void k_process(const float* __restrict__ scores) {
    unsigned int s = blockIdx.x * blockDim.x + threadIdx.x;
    if (s >= HASH_SIZE) return;
    unsigned int key = g_keys[s];
    if (key == EMPTY_KEY) return;
    unsigned int c = g_cnts[s];

    float c0 = (float)( c        & 0xFFu);
    float c1 = (float)((c >> 8 ) & 0xFFu);
    float c2 = (float)((c >> 16) & 0xFFu);
    float c3 = (float)((c >> 24) & 0xFFu);
    float ctot = c0 + c1 + c2 + c3;

    unsigned int i = key >> 13;
    unsigned int j = key & 8191u;
    float si = __ldg(scores + i);
    float sj = __ldg(scores + j);

    #pragma unroll
    for (int h = 0; h < H_HEADS; h++) {
        float a = (si * g_wsrc[h] + sj * g_wtgt[h]) * ctot
                + c0 * g_embterm[h * T_TYPES + 0]
                + c1 * g_embterm[h * T_TYPES + 1]
                + c2 * g_embterm[h * T_TYPES + 2]
                + c3 * g_embterm[h * T_TYPES + 3];
        a = (a >= 0.f) ? a : NEG_SLOPE * a;
        float ex = __expf(a) - 1.f;
        atomicAdd(&g_denom[h * N_NODES + i], ex);
        atomicAdd(&g_num  [h * N_NODES + i], ex * sj);
    }
}

// ---------------------------------------------------------------------------
// 5) Finalize: out_i = mean_h (S_total + num) / (N + denom)
// ---------------------------------------------------------------------------
__global__ void k_final(float* __restrict__ out) {
    int i = blockIdx.x * blockDim.x + threadIdx.x;
    if (i >= N_NODES) return;
    float st  = g_stotal;
    float acc = 0.f;
    #pragma unroll
    for (int h = 0; h < H_HEADS; h++) {
        acc += (st + g_num[h * N_NODES + i]) /
               ((float)N_NODES + g_denom[h * N_NODES + i]);
    }
    out[i] = acc * (1.f / (float)H_HEADS);
}

// ---------------------------------------------------------------------------
extern "C" void kernel_launch(void* const* d_in, const int* in_sizes, int n_in,
                              void* d_out, int out_size) {
    const float* scores = (const float*)d_in[0];   // (N, 1)
    const float* emb    = (const float*)d_in[1];   // (T, D)
    const int*   ei     = (const int*)  d_in[2];   // (T, 2, E)
    const float* W      = (const float*)d_in[3];   // (H, D+2, 1)
    float*       out    = (float*)d_out;           // (N, 1)

    k_clear  <<<4096, 256>>>();
    k_params <<<1, 256>>>(scores, emb, W);
    k_insert <<<(T_TYPES * E_EDGES) / 256, 256>>>(ei);
    k_process<<<HASH_SIZE / 256, 256>>>(scores);
    k_final  <<<N_NODES / 256, 256>>>(out);
}